// round 15
// baseline (speedup 1.0000x reference)
#include <cuda_runtime.h>
#include <cstdint>

// out[b, j] = relu( sum_d x[b,d] * (gamma*W3[j,d] + W4[j,d]) )
// softmax over size-1 axis == 1 -> attention collapses; W1/W2 dead.
//
// R12 lesson: L1 lane-byte law is PATH-INDEPENDENT (broadcast LDG == broadcast LDS
// ~= 4 cyc per 16B warp-load). Fix what's actually fixable: (1) d-pair fma2
// accumulation -> x feeds fma2 straight from LDG.128, zero packing MOVs, shorter
// dep chains; (2) occupancy 2->3 blocks/SM for latency hiding; (3) full-tile L2
// prefetch; (4) streaming stores.

#define B_ROWS    262144
#define DICTD     20
#define DPAIRS    (DICTD / 2)             // 10 d-pairs
#define JCOLS     200
#define RPT       4                       // rows per thread per tile
#define CPT       4                       // cols per thread
#define NQUADS    (JCOLS / CPT)           // 50
#define NGROUPS   4                       // row-groups per tile
#define TILE_ROWS (NGROUPS * RPT)         // 16
#define NTHREADS  (NGROUPS * NQUADS)      // 200
#define NTILES    (B_ROWS / TILE_ROWS)    // 16384
#define NBLOCKS   444                     // 3 per SM

typedef unsigned long long ull;

__device__ __forceinline__ ull pack2(float lo, float hi) {
    ull r;
    asm("mov.b64 %0, {%1, %2};" : "=l"(r) : "f"(lo), "f"(hi));
    return r;
}
// Packed dual fp32 FMA (sm_100+): 2 MACs/inst at rt_SMSP=2.
__device__ __forceinline__ ull fma2(ull a, ull b, ull c) {
    ull d;
    asm("fma.rn.f32x2 %0, %1, %2, %3;" : "=l"(d) : "l"(a), "l"(b), "l"(c));
    return d;
}
__device__ __forceinline__ void prefetch_l2(const void* p) {
    asm volatile("prefetch.global.L2 [%0];" :: "l"(p));
}
// (even-d sum, odd-d sum) -> relu(lo + hi)
__device__ __forceinline__ float hsum_relu(ull acc) {
    float2 f = *reinterpret_cast<float2*>(&acc);
    return fmaxf(f.x + f.y, 0.0f);
}

__global__ void __launch_bounds__(NTHREADS, 3)
fused_relu_gemm_kernel(const float* __restrict__ x,
                       const float* __restrict__ W3,
                       const float* __restrict__ W4,
                       const float* __restrict__ gamma,
                       float* __restrict__ out)
{
    const int tid = threadIdx.x;
    const int g   = tid / NQUADS;          // 0..3  row-group (4 rows)
    const int q   = tid % NQUADS;          // 0..49 col-quad
    const int j0  = q * CPT;

    // ---- one-time: effective weights as (d, d+1) pairs, 4 cols x 10 pairs ----
    const float gm = __ldg(gamma);
    ull w[CPT][DPAIRS];                    // 40 ull = 80 regs
#pragma unroll
    for (int c = 0; c < CPT; c++) {
#pragma unroll
        for (int dp = 0; dp < DPAIRS; dp++) {
            const int base = (j0 + c) * DICTD + 2 * dp;
            float a = fmaf(gm, __ldg(&W3[base + 0]), __ldg(&W4[base + 0]));
            float b = fmaf(gm, __ldg(&W3[base + 1]), __ldg(&W4[base + 1]));
            w[c][dp] = pack2(a, b);
        }
    }

    for (int tile = blockIdx.x; tile < NTILES; tile += NBLOCKS) {
        const int rowbase = tile * TILE_ROWS + g * RPT;

        // full-tile prefetch, one tile ahead: 16 rows x 80B = 1280B = 10 lines
        const int nt = tile + NBLOCKS;
        if (nt < NTILES && tid < 10)
            prefetch_l2(x + nt * (TILE_ROWS * DICTD) + tid * 32);

#pragma unroll
        for (int r = 0; r < RPT; r++) {
            const int row = rowbase + r;
            const ulonglong2* xp =
                reinterpret_cast<const ulonglong2*>(x + row * DICTD);  // 5 x 16B

            ull a0 = 0, a1 = 0, a2 = 0, a3 = 0;   // 4 independent chains
#pragma unroll
            for (int k = 0; k < 5; k++) {
                const ulonglong2 v = __ldg(&xp[k]);   // d-pairs (2k, 2k+1) raw
                a0 = fma2(v.x, w[0][2 * k], a0); a0 = fma2(v.y, w[0][2 * k + 1], a0);
                a1 = fma2(v.x, w[1][2 * k], a1); a1 = fma2(v.y, w[1][2 * k + 1], a1);
                a2 = fma2(v.x, w[2][2 * k], a2); a2 = fma2(v.y, w[2][2 * k + 1], a2);
                a3 = fma2(v.x, w[3][2 * k], a3); a3 = fma2(v.y, w[3][2 * k + 1], a3);
            }

            // horizontal add + relu + streaming STG.128 (lanes = consecutive quads)
            const float4 o = make_float4(hsum_relu(a0), hsum_relu(a1),
                                         hsum_relu(a2), hsum_relu(a3));
            __stcs(reinterpret_cast<float4*>(&out[row * JCOLS + j0]), o);
        }
    }
}

extern "C" void kernel_launch(void* const* d_in, const int* in_sizes, int n_in,
                              void* d_out, int out_size)
{
    // metadata order: x, W1, W2, W3, W4, gamma  (W1/W2 mathematically dead)
    const float* x     = (const float*)d_in[0];
    const float* W3    = (const float*)d_in[3];
    const float* W4    = (const float*)d_in[4];
    const float* gamma = (const float*)d_in[5];
    float*       out   = (float*)d_out;

    fused_relu_gemm_kernel<<<NBLOCKS, NTHREADS>>>(x, W3, W4, gamma, out);
}